// round 4
// baseline (speedup 1.0000x reference)
#include <cuda_runtime.h>

// out[b, q, j] = float( max(0, q - 127) + j )   for B=8, Q=4096, K=64.
//
// Derivation: the reference masks the local window [q-127, q] to +inf and
// future (k>q) to -inf before jax.lax.top_k(..., 64). top_k is stable
// (lowest index wins ties), so the top-64 are always the 64 smallest
// indices of the +inf window (padded by -inf ties ascending from q+1 when
// q < 63) = max(0,q-127)+0..63. Input I never affects the result. Output
// dtype float32 (confirmed R1/R2).
//
// R3 post-mortem: 16 stores/thread (128 CTAs) starved the chip (occ 13%).
// R2: 1 store/thread (2048 CTAs) was issue-bound on setup. Optimum between:
// 4x float4 stores per thread, 512 CTAs -> good occupancy AND amortized setup.

__global__ void TokenSelector_17755394801797_kernel(float4* __restrict__ out) {
    int tid = blockIdx.x * blockDim.x + threadIdx.x;   // 0..131071, quarter-row each
    int lin = tid << 4;                                // first element index (16 per thread)
    int j   = lin & 63;                                // 0, 16, 32, or 48
    int q   = (lin >> 6) & 4095;
    int start = q - 127;
    if (start < 0) start = 0;
    float base = (float)(start + j);

    float4* p = out + (tid << 2);                      // 4 float4 per thread

#pragma unroll
    for (int i = 0; i < 4; i++) {
        float b = base + (float)(4 * i);
        float4 v;
        v.x = b;
        v.y = b + 1.0f;
        v.z = b + 2.0f;
        v.w = b + 3.0f;
        p[i] = v;
    }
}

extern "C" void kernel_launch(void* const* d_in, const int* in_sizes, int n_in,
                              void* d_out, int out_size) {
    (void)d_in; (void)in_sizes; (void)n_in; (void)out_size;
    // 2,097,152 elements / 16 per thread = 131,072 threads
    int threads = 256;
    int blocks = 131072 / threads;                     // 512 blocks
    TokenSelector_17755394801797_kernel<<<blocks, threads>>>((float4*)d_out);
}

// round 5
// speedup vs baseline: 1.3023x; 1.3023x over previous
#include <cuda_runtime.h>
#include <cstdint>

// out[b, q, j] = float( max(0, q - 127) + j )   for B=8, Q=4096, K=64.
//
// Derivation: reference masks local window [q-127, q] to +inf, future to
// -inf, then stable top_k(64) -> always the 64 lowest window indices
// = max(0,q-127)+0..63. Input I is irrelevant. Output dtype fp32.
//
// R3/R4 post-mortem: any STG-based kernel floors at ~5.3us because
// 524,288 x STG.128 at 12 cyc issue cost / 592 SMSPs ~ 10.6k cycles.
// Switch to TMA bulk stores (UTMASTG, ~6300 B/cyc chip cap ~ 1.3us for
// 8.4 MB) and exploit batch redundancy: fill each 32-row chunk in SMEM
// once, bulk-store it 8x (once per batch). SMEM fill = 1 MB total.

static constexpr int ROWS_PER_CTA = 32;           // 4096 / 128
static constexpr int CHUNK_BYTES  = ROWS_PER_CTA * 64 * 4;  // 8192
static constexpr long long BATCH_BYTES = 4096LL * 64 * 4;   // 1 MB

__global__ void __launch_bounds__(256, 1)
TokenSelector_17755394801797_kernel(char* __restrict__ out) {
    __shared__ alignas(128) float tile[ROWS_PER_CTA * 64];

    int tid = threadIdx.x;
    int q0  = blockIdx.x * ROWS_PER_CTA;

    // Fill 32 rows x 64 floats = 512 float4; 2 per thread.
#pragma unroll
    for (int t = 0; t < 2; t++) {
        int f  = tid + t * 256;            // float4 index 0..511
        int r  = f >> 4;                   // row within chunk
        int j4 = (f & 15) << 2;            // column (multiple of 4)
        int q  = q0 + r;
        int start = q - 127;
        if (start < 0) start = 0;
        float b = (float)(start + j4);
        float4 v;
        v.x = b; v.y = b + 1.0f; v.z = b + 2.0f; v.w = b + 3.0f;
        reinterpret_cast<float4*>(tile)[f] = v;
    }
    __syncthreads();

    if (tid == 0) {
        asm volatile("fence.proxy.async.shared::cta;" ::: "memory");
        uint32_t src;
        asm("{ .reg .u64 t; cvta.to.shared.u64 t, %1; cvt.u32.u64 %0, t; }"
            : "=r"(src) : "l"((const void*)tile));

        long long chunk_off = (long long)blockIdx.x * CHUNK_BYTES;
#pragma unroll
        for (int b = 0; b < 8; b++) {
            char* dst = out + b * BATCH_BYTES + chunk_off;
            asm volatile(
                "cp.async.bulk.global.shared::cta.bulk_group [%0], [%1], %2;"
                :: "l"(dst), "r"(src), "n"(CHUNK_BYTES) : "memory");
        }
        asm volatile("cp.async.bulk.commit_group;" ::: "memory");
        asm volatile("cp.async.bulk.wait_group.read 0;" ::: "memory");
    }
}

extern "C" void kernel_launch(void* const* d_in, const int* in_sizes, int n_in,
                              void* d_out, int out_size) {
    (void)d_in; (void)in_sizes; (void)n_in; (void)out_size;
    TokenSelector_17755394801797_kernel<<<128, 256>>>((char*)d_out);
}